// round 2
// baseline (speedup 1.0000x reference)
#include <cuda_runtime.h>

// SplineLoss on GB300: reference samples the spline only at integer knot
// times (t = 0,10,...,1020) where dx == 0.0 exactly, so all moment terms
// vanish and the loss is EXACTLY the strided MSE:
//   mean over t in {0,10,...,1020}, b, d of (true[b,t,d] - pred[b,t,d])^2
//
// R2: single-launch kernel. R1 showed 2 graph nodes cost ~8.7us while the
// actual memory work is ~1us (DRAM 0%, issue 3.6% on finalize). Fuse the
// final reduction into the same launch via the last-block pattern
// (threadfence + atomic ticket; deterministic fixed-order reduction).

#define B_ 128
#define T_ 1024
#define D_ 64
#define S_ 103            // sample times 0,10,...,1020
#define STEP_ 10
#define D4_ (D_ / 4)      // 16 float4 per sampled row
#define TOTAL4_ (B_ * S_ * D4_)          // 210944 float4 pairs
#define COUNT_ ((float)(B_ * S_ * D_))   // 843776 elements in the mean

constexpr int NBLK = 256;
constexpr int NTHR = 256;

__device__ float g_partials[NBLK];
__device__ unsigned int g_ticket = 0;   // reset by the last block each call

__global__ __launch_bounds__(NTHR) void spline_mse_fused(
    const float* __restrict__ yt, const float* __restrict__ yp,
    float* __restrict__ out)
{
    float acc = 0.0f;
    const float4* __restrict__ a4 = (const float4*)yt;
    const float4* __restrict__ b4 = (const float4*)yp;

    #pragma unroll 4
    for (int i = blockIdx.x * NTHR + threadIdx.x; i < TOTAL4_; i += NBLK * NTHR) {
        int d4   = i & (D4_ - 1);
        int rest = i >> 4;
        int s    = rest % S_;
        int b    = rest / S_;
        int addr = (b * T_ + s * STEP_) * D4_ + d4;
        float4 va = __ldg(&a4[addr]);
        float4 vb = __ldg(&b4[addr]);
        float e0 = va.x - vb.x;
        float e1 = va.y - vb.y;
        float e2 = va.z - vb.z;
        float e3 = va.w - vb.w;
        acc = fmaf(e0, e0, acc);
        acc = fmaf(e1, e1, acc);
        acc = fmaf(e2, e2, acc);
        acc = fmaf(e3, e3, acc);
    }

    // block reduce
    #pragma unroll
    for (int o = 16; o > 0; o >>= 1)
        acc += __shfl_down_sync(0xffffffffu, acc, o);

    __shared__ float sh[NTHR / 32];
    if ((threadIdx.x & 31) == 0) sh[threadIdx.x >> 5] = acc;
    __syncthreads();

    if (threadIdx.x < 32) {
        float v = (threadIdx.x < NTHR / 32) ? sh[threadIdx.x] : 0.0f;
        #pragma unroll
        for (int o = 16; o > 0; o >>= 1)
            v += __shfl_down_sync(0xffffffffu, v, o);
        if (threadIdx.x == 0) g_partials[blockIdx.x] = v;
    }

    // last-block finalize (deterministic: fixed-order tree over g_partials)
    __shared__ bool s_last;
    if (threadIdx.x == 0) {
        __threadfence();                                  // publish partial
        unsigned int t = atomicAdd(&g_ticket, 1u);
        s_last = (t == NBLK - 1);
    }
    __syncthreads();
    if (!s_last) return;

    __threadfence();                                      // see all partials
    float v = g_partials[threadIdx.x];                    // NBLK == NTHR
    #pragma unroll
    for (int o = 16; o > 0; o >>= 1)
        v += __shfl_down_sync(0xffffffffu, v, o);
    __shared__ float sh2[NTHR / 32];
    if ((threadIdx.x & 31) == 0) sh2[threadIdx.x >> 5] = v;
    __syncthreads();
    if (threadIdx.x < 32) {
        float w = (threadIdx.x < NTHR / 32) ? sh2[threadIdx.x] : 0.0f;
        #pragma unroll
        for (int o = 16; o > 0; o >>= 1)
            w += __shfl_down_sync(0xffffffffu, w, o);
        if (threadIdx.x == 0) {
            out[0] = w / COUNT_;
            g_ticket = 0;                                 // reset for next call
        }
    }
}

extern "C" void kernel_launch(void* const* d_in, const int* in_sizes, int n_in,
                              void* d_out, int out_size)
{
    const float* yt = (const float*)d_in[0];   // true_frames
    const float* yp = (const float*)d_in[1];   // predicted_frames
    spline_mse_fused<<<NBLK, NTHR>>>(yt, yp, (float*)d_out);
}

// round 3
// speedup vs baseline: 1.0037x; 1.0037x over previous
#include <cuda_runtime.h>

// SplineLoss on GB300: reference samples the spline only at integer knot
// times (t = 0,10,...,1020) where dx == 0.0 exactly, so all moment terms
// vanish and the loss is EXACTLY the strided MSE over sampled rows:
//   mean over s in {0..102}, b, d of (true[b,10s,d] - pred[b,10s,d])^2
//
// R3: critical-chain minimization. R1/R2 showed time tracks dependent-work
// cycles (each kernel ~4us regardless of size -> low effective clock), so:
//  - 103 blocks (one per sample time), single wave on 148 SMs
//  - 8 independent float4-pair loads per thread, shift/mask addressing only,
//    front-batched (MLP=16) so DRAM latency is paid once
//  - tail: one STG + fence + ticket; last block's warp 0 reduces 103 partials

#define T_ 1024
#define D4_ 16                 // 64 floats per row = 16 float4
#define S_ 103                 // sample times 0,10,...,1020
#define ROW_STRIDE4_ (T_ * D4_)            // float4 stride between batches
#define COUNT_ 843776.0f       // 128 * 103 * 64

constexpr int NTHR = 256;      // 128 rows * 16 float4 = 2048 = 8 * 256

__device__ float g_partials[S_];
__device__ unsigned int g_ticket = 0;      // reset by last block each call

__global__ __launch_bounds__(NTHR) void spline_mse_onewave(
    const float* __restrict__ yt, const float* __restrict__ yp,
    float* __restrict__ out)
{
    const int s = blockIdx.x;              // 0..102
    const int base = s * 10 * D4_;         // float4 offset of row t=10s, batch 0
    const float4* __restrict__ a4 = (const float4*)yt + base;
    const float4* __restrict__ b4 = (const float4*)yp + base;

    const int d4 = threadIdx.x & (D4_ - 1);
    const int b0 = threadIdx.x >> 4;       // starting batch, step 16 per iter

    // 16 independent LDG.128, front-batched; then FMA tail.
    float4 va[8], vb[8];
    #pragma unroll
    for (int k = 0; k < 8; k++) {
        int addr = (b0 + k * 16) * ROW_STRIDE4_ + d4;
        va[k] = __ldg(&a4[addr]);
        vb[k] = __ldg(&b4[addr]);
    }

    float acc = 0.0f;
    #pragma unroll
    for (int k = 0; k < 8; k++) {
        float e0 = va[k].x - vb[k].x;
        float e1 = va[k].y - vb[k].y;
        float e2 = va[k].z - vb[k].z;
        float e3 = va[k].w - vb[k].w;
        acc = fmaf(e0, e0, acc);
        acc = fmaf(e1, e1, acc);
        acc = fmaf(e2, e2, acc);
        acc = fmaf(e3, e3, acc);
    }

    // block reduce (fixed order -> deterministic)
    #pragma unroll
    for (int o = 16; o > 0; o >>= 1)
        acc += __shfl_down_sync(0xffffffffu, acc, o);

    __shared__ float sh[NTHR / 32];
    if ((threadIdx.x & 31) == 0) sh[threadIdx.x >> 5] = acc;
    __syncthreads();

    if (threadIdx.x >= 32) return;         // only warp 0 continues

    float v = (threadIdx.x < NTHR / 32) ? sh[threadIdx.x] : 0.0f;
    #pragma unroll
    for (int o = 4; o > 0; o >>= 1)        // 8 lanes carry data
        v += __shfl_down_sync(0xffffffffu, v, o);

    // publish partial + take ticket (lane 0), broadcast within warp 0
    unsigned int ticket = 0;
    if (threadIdx.x == 0) {
        g_partials[s] = v;
        __threadfence();                   // partial visible before ticket
        ticket = atomicAdd(&g_ticket, 1u);
    }
    ticket = __shfl_sync(0xffffffffu, ticket, 0);
    if (ticket != S_ - 1) return;          // not the last block

    __threadfence();                       // acquire: see all partials
    float tot = 0.0f;
    for (int k = threadIdx.x; k < S_; k += 32)   // fixed order per lane
        tot += g_partials[k];
    #pragma unroll
    for (int o = 16; o > 0; o >>= 1)
        tot += __shfl_down_sync(0xffffffffu, tot, o);

    if (threadIdx.x == 0) {
        out[0] = tot / COUNT_;
        g_ticket = 0;                      // reset for next launch
    }
}

extern "C" void kernel_launch(void* const* d_in, const int* in_sizes, int n_in,
                              void* d_out, int out_size)
{
    const float* yt = (const float*)d_in[0];   // true_frames
    const float* yp = (const float*)d_in[1];   // predicted_frames
    spline_mse_onewave<<<S_, NTHR>>>(yt, yp, (float*)d_out);
}